// round 15
// baseline (speedup 1.0000x reference)
#include <cuda_runtime.h>
#include <cuda_fp16.h>
#include <cstdint>

// ---------------- problem dimensions ----------------
#define NM    1500
#define ND    800
#define NN    2300
#define NNP   2304          // NN padded to mult of 128
#define CC    128
#define HH    8
#define HC    1024
#define HC2   2048          // xl|xr concat
#define EE    80000
#define ETOT  (EE + NN)
#define PP    40000
#define NPAIR 80000
#define FDIM  2778
#define FPAD  2816          // mult of 64 / 128
#define D1    1389
#define D1P   1408
#define D2    694
#define D2P   704
#define D2NT  768
#define D3    463
#define D3P   464
#define D3NT  512

// ---------------- scratch ----------------
__device__ float    g_h    [NNP * CC];
__device__ __half   g_hh   [NNP * CC];
__device__ float    g_xlr  [NNP * HC2];     // [n][0:1024]=xl, [n][1024:2048]=xr
__device__ float    g_blr  [HC2];
__device__ __half   g_gath [NNP * HC];      // half(gat + gbias), pad rows zero
__device__ float    g_cnn  [NN * FDIM];     // fallback cnn buffer
__device__ __half   g_cnnh [(size_t)NNP * FPAD];  // half mirror of cnn (pad cols zero)
__device__ int      g_cnt  [NN];
__device__ int      g_off  [NN + 1];
__device__ int      g_sorted[ETOT];
__device__ __half   g_featsh[(size_t)NPAIR * FPAD];
__device__ __half   g_h1h  [(size_t)NPAIR * D1P];
__device__ __half   g_h2h  [(size_t)NPAIR * D2P];
__device__ __half   g_w1th [(size_t)D1P  * FPAD];
__device__ __half   g_w2th [(size_t)D2NT * D1P];
__device__ __half   g_w3th [(size_t)D3NT * D2P];
__device__ __half   g_wlrth[HC2 * CC];      // rows 0-1023: Wl^T, 1024-2047: Wr^T
__device__ __half   g_bth  [(size_t)FPAD * HC];   // conv-as-GEMM weight, [c][k]
__device__ float    g_cb   [FPAD];                 // conv bias per feature

// ---------------- fp16 mma.sync GEMM, BK=64, 3-stage, 1 sync/iter, occ 2 ----------------
#define HROWB 72
#define HTILE2 (128 * HROWB * 2)      // 18432 B
#define HSTG2  (2 * HTILE2)           // 36864 B
#define SMEM_HC (3 * HSTG2)           // 110592 B

#define LDSM_X4(r0, r1, r2, r3, addr) \
    asm volatile("ldmatrix.sync.aligned.m8n8.x4.shared.b16 {%0,%1,%2,%3}, [%4];" \
        : "=r"(r0), "=r"(r1), "=r"(r2), "=r"(r3) : "r"(addr))

__global__ void __launch_bounds__(256, 2)
gemm_hc(const __half* __restrict__ A, const __half* __restrict__ Bt,
        const float* __restrict__ bias, void* __restrict__ Cv,
        int Nreal, int Kp, int ldc, int Mreal, float slope, int fp32_out,
        const float* __restrict__ dotw, float* __restrict__ dotout,
        __half* __restrict__ Cv2, int ldc2)
{
    extern __shared__ __half sm[];
    const int tid  = threadIdx.x;
    const int lane = tid & 31, wid = tid >> 5;
    const int g = lane >> 2, tg = lane & 3;
    const int wm = wid & 1, wn = wid >> 1;
    const int m0 = blockIdx.y * 128, n0 = blockIdx.x * 128;
    const unsigned smb = (unsigned)__cvta_generic_to_shared(sm);

    float acc[4][4][4];
#pragma unroll
    for (int a = 0; a < 4; a++)
#pragma unroll
        for (int b = 0; b < 4; b++)
#pragma unroll
            for (int c = 0; c < 4; c++) acc[a][b][c] = 0.f;

    const unsigned a_off = (unsigned)(((lane & 15) * HROWB + (lane >> 4) * 8) * 2);
    const unsigned b_off = (unsigned)(((((lane >> 4) << 3) + (lane & 7)) * HROWB
                                      + ((lane >> 3) & 1) * 8) * 2);

    auto fill = [&](int s, int kt) {
        unsigned ab = smb + (unsigned)s * HSTG2;
        unsigned bb = ab + HTILE2;
#pragma unroll
        for (int p = 0; p < 4; p++) {
            int i = p * 256 + tid;
            int row = i >> 3, c = i & 7;
            unsigned off = (unsigned)((row * HROWB + c * 8) * 2);
            const __half* srcA = A  + (size_t)(m0 + row) * Kp + kt + c * 8;
            const __half* srcB = Bt + (size_t)(n0 + row) * Kp + kt + c * 8;
            asm volatile("cp.async.cg.shared.global [%0], [%1], 16;" :: "r"(ab + off), "l"(srcA));
            asm volatile("cp.async.cg.shared.global [%0], [%1], 16;" :: "r"(bb + off), "l"(srcB));
        }
        asm volatile("cp.async.commit_group;" ::: "memory");
    };

    const int T = Kp >> 6;
    fill(0, 0);
    if (T > 1) fill(1, 64);

    for (int t = 0; t < T; ++t) {
        if (t < T - 1) asm volatile("cp.async.wait_group 1;" ::: "memory");
        else           asm volatile("cp.async.wait_group 0;" ::: "memory");
        __syncthreads();
        if (t + 2 < T) fill((t + 2) % 3, (t + 2) * 64);

        unsigned ab = smb + (unsigned)(t % 3) * HSTG2;
        unsigned bb = ab + HTILE2;
#pragma unroll
        for (int kk = 0; kk < 4; ++kk) {
            const unsigned kb = (unsigned)(kk * 32);
            unsigned a[4][4], b[2][4];
#pragma unroll
            for (int mt = 0; mt < 4; ++mt) {
                unsigned ad = ab + (unsigned)((wm * 64 + mt * 16) * HROWB * 2) + a_off + kb;
                LDSM_X4(a[mt][0], a[mt][1], a[mt][2], a[mt][3], ad);
            }
#pragma unroll
            for (int np = 0; np < 2; ++np) {
                unsigned bd = bb + (unsigned)((wn * 32 + np * 16) * HROWB * 2) + b_off + kb;
                LDSM_X4(b[np][0], b[np][1], b[np][2], b[np][3], bd);
            }
#pragma unroll
            for (int mt = 0; mt < 4; ++mt)
#pragma unroll
                for (int nt = 0; nt < 4; ++nt) {
                    unsigned b0 = b[nt >> 1][(nt & 1) * 2];
                    unsigned b1 = b[nt >> 1][(nt & 1) * 2 + 1];
                    asm volatile(
                        "mma.sync.aligned.m16n8k16.row.col.f32.f16.f16.f32 "
                        "{%0,%1,%2,%3}, {%4,%5,%6,%7}, {%8,%9}, {%0,%1,%2,%3};\n"
                        : "+f"(acc[mt][nt][0]), "+f"(acc[mt][nt][1]),
                          "+f"(acc[mt][nt][2]), "+f"(acc[mt][nt][3])
                        : "r"(a[mt][0]), "r"(a[mt][1]), "r"(a[mt][2]), "r"(a[mt][3]),
                          "r"(b0), "r"(b1));
                }
        }
    }

    if (dotw) {
        float dsum[4][2];
#pragma unroll
        for (int mt = 0; mt < 4; ++mt) { dsum[mt][0] = 0.f; dsum[mt][1] = 0.f; }
#pragma unroll
        for (int mt = 0; mt < 4; ++mt)
#pragma unroll
            for (int nt = 0; nt < 4; ++nt) {
                int c0 = n0 + wn * 32 + nt * 8 + 2 * tg;
#pragma unroll
                for (int hr = 0; hr < 2; ++hr) {
                    float p = 0.f;
                    if (c0 < Nreal) {
                        float v = acc[mt][nt][hr * 2] + __ldg(&bias[c0]);
                        v = v > 0.f ? v : slope * v;
                        p += v * __ldg(&dotw[c0]);
                    }
                    if (c0 + 1 < Nreal) {
                        float v = acc[mt][nt][hr * 2 + 1] + __ldg(&bias[c0 + 1]);
                        v = v > 0.f ? v : slope * v;
                        p += v * __ldg(&dotw[c0 + 1]);
                    }
                    dsum[mt][hr] += p;
                }
            }
#pragma unroll
        for (int mt = 0; mt < 4; ++mt)
#pragma unroll
            for (int hr = 0; hr < 2; ++hr) {
                float p = dsum[mt][hr];
                p += __shfl_down_sync(0xffffffffu, p, 1, 4);
                p += __shfl_down_sync(0xffffffffu, p, 2, 4);
                if (tg == 0) {
                    int r = m0 + wm * 64 + mt * 16 + g + hr * 8;
                    atomicAdd(&dotout[r], p);
                }
            }
        return;
    }

#pragma unroll
    for (int mt = 0; mt < 4; ++mt) {
#pragma unroll
        for (int nt = 0; nt < 4; ++nt) {
            int r0 = m0 + wm * 64 + mt * 16 + g;
            int c0 = n0 + wn * 32 + nt * 8 + 2 * tg;
            if (c0 >= ldc && c0 >= ldc2) continue;
#pragma unroll
            for (int hr = 0; hr < 2; ++hr) {
                int r = r0 + hr * 8;
                float v0 = 0.f, v1 = 0.f;
                if (c0 < Nreal) {
                    v0 = acc[mt][nt][hr * 2] + __ldg(&bias[c0]);
                    v0 = v0 > 0.f ? v0 : slope * v0;
                }
                if (c0 + 1 < Nreal) {
                    v1 = acc[mt][nt][hr * 2 + 1] + __ldg(&bias[c0 + 1]);
                    v1 = v1 > 0.f ? v1 : slope * v1;
                }
                if (c0 < ldc && r < Mreal) {
                    if (fp32_out) {
                        *reinterpret_cast<float2*>(&((float*)Cv)[(size_t)r * ldc + c0])
                            = make_float2(v0, v1);
                    } else {
                        *reinterpret_cast<__half2*>(&((__half*)Cv)[(size_t)r * ldc + c0])
                            = __floats2half2_rn(v0, v1);
                    }
                }
                if (Cv2 && c0 < ldc2) {
                    *reinterpret_cast<__half2*>(&Cv2[(size_t)r * ldc2 + c0])
                        = __floats2half2_rn(v0, v1);
                }
            }
        }
    }
}

// ---------------- conv-as-GEMM weight build: Bt[c][k] + bias ----------------
__global__ void k_bbuild(const float* __restrict__ cw1,  const float* __restrict__ cb1,
                         const float* __restrict__ cw4,  const float* __restrict__ cb4,
                         const float* __restrict__ cw16, const float* __restrict__ cb16,
                         const float* __restrict__ cw32, const float* __restrict__ cb32)
{
    int i = blockIdx.x * blockDim.x + threadIdx.x;
    if (i >= FPAD * HC) return;
    int c = i >> 10, k = i & 1023;
    float val = 0.f;
    float bv = 0.f;
    if (c < FDIM) {
        int kh = k >> 7, xx = k & 127;
        const float* w; const float* cb; int kw, o, x0;
        if (c < 768)       { int j = c;        kw = 1;  w = cw1;  cb = cb1;  o = j / 128; x0 = j % 128; }
        else if (c < 1518) { int j = c - 768;  kw = 4;  w = cw4;  cb = cb4;  o = j / 125; x0 = j % 125; }
        else if (c < 2196) { int j = c - 1518; kw = 16; w = cw16; cb = cb16; o = j / 113; x0 = j % 113; }
        else               { int j = c - 2196; kw = 32; w = cw32; cb = cb32; o = j / 97;  x0 = j % 97;  }
        int dx = xx - x0;
        if (dx >= 0 && dx < kw) val = w[(o * 8 + kh) * kw + dx];
        bv = cb[o];
    }
    g_bth[(size_t)c * HC + k] = __float2half_rn(val);
    if (k == 0) g_cb[c] = bv;
}

// ---------------- tiled transpose + fp16: dst[n][k] = src[k][n] ----------------
__global__ void k_transp(const float* __restrict__ src, __half* __restrict__ dst,
                         int Ktrue, int Ntrue, int Kp, int Npad)
{
    __shared__ float t[32][33];
    int k0 = blockIdx.x * 32, n0 = blockIdx.y * 32;
    int tx = threadIdx.x, ty = threadIdx.y;
#pragma unroll
    for (int i = 0; i < 4; i++) {
        int k = k0 + ty + i * 8, n = n0 + tx;
        t[ty + i * 8][tx] = (k < Ktrue && n < Ntrue) ? src[(size_t)k * Ntrue + n] : 0.f;
    }
    __syncthreads();
#pragma unroll
    for (int i = 0; i < 4; i++) {
        int n = n0 + ty + i * 8, k = k0 + tx;
        if (n < Npad && k < Kp)
            dst[(size_t)n * Kp + k] = __float2half_rn(t[tx][ty + i * 8]);
    }
}

// zero h, init CSR counts, zero pred region, labels, concat bias, zero gath pad rows
__global__ void k_zero_init(float* p, int n, float* out, int write_labels,
                            const float* __restrict__ bl, const float* __restrict__ br)
{
    int i = blockIdx.x * blockDim.x + threadIdx.x;
    if (i < n) p[i] = 0.f;
    if (i < NN) g_cnt[i] = 1;
    if (i < HC) { g_blr[i] = bl[i]; g_blr[HC + i] = br[i]; }
    if (i < (NNP - NN) * HC) g_gath[NN * HC + i] = __float2half_rn(0.f);
    if (i < NPAIR) {
        out[i] = 0.f;
        if (write_labels) out[NPAIR + i] = (i < PP) ? 1.f : 0.f;
    }
}

__global__ void k_f2h(const float* __restrict__ src, __half* __restrict__ dst, int n)
{
    int i = blockIdx.x * blockDim.x + threadIdx.x;
    if (i < n) dst[i] = __float2half_rn(src[i]);
}

__global__ void k_sig(float* __restrict__ out)
{
    int i = blockIdx.x * blockDim.x + threadIdx.x;
    if (i < NPAIR) out[i] = 1.f / (1.f + expf(-out[i]));
}

// ---------------- fp32 tiled GEMM with split-K ----------------
#define BM 128
#define BN 128
#define BKK 8
#define TM 8
#define TN 8

__global__ void __launch_bounds__(256, 2)
sgemm(const float* __restrict__ A, const float* __restrict__ B,
      const float* __restrict__ bias, float* __restrict__ C,
      int M, int N, int K, int act, float slope)
{
    __shared__ float As[BKK][BM];
    __shared__ float Bs[BKK][BN];

    const int tid = threadIdx.x;
    const int m0 = blockIdx.y * BM;
    const int n0 = blockIdx.x * BN;

    int chunk = (K + gridDim.z - 1) / gridDim.z;
    int kb = blockIdx.z * chunk;
    int ke = min(K, kb + chunk);

    const int arow = tid >> 1;
    const int acol = (tid & 1) * 4;
    const int brow = tid >> 5;
    const int bcol = (tid & 31) * 4;
    const int tr = (tid >> 4) * TM;
    const int tc = (tid & 15) * TN;

    float acc[TM][TN];
#pragma unroll
    for (int i = 0; i < TM; i++)
#pragma unroll
        for (int j = 0; j < TN; j++) acc[i][j] = 0.f;

    for (int k0 = kb; k0 < ke; k0 += BKK) {
#pragma unroll
        for (int j = 0; j < 4; j++) {
            int k = k0 + acol + j;
            int mm = m0 + arow;
            As[acol + j][arow] = (mm < M && k < ke) ? A[(size_t)mm * K + k] : 0.f;
        }
#pragma unroll
        for (int j = 0; j < 4; j++) {
            int k = k0 + brow;
            int n = n0 + bcol + j;
            Bs[brow][bcol + j] = (k < ke && n < N) ? B[(size_t)k * N + n] : 0.f;
        }
        __syncthreads();
#pragma unroll
        for (int kk = 0; kk < BKK; kk++) {
            float ra[TM], rb[TN];
#pragma unroll
            for (int i = 0; i < TM; i++) ra[i] = As[kk][tr + i];
#pragma unroll
            for (int j = 0; j < TN; j++) rb[j] = Bs[kk][tc + j];
#pragma unroll
            for (int i = 0; i < TM; i++)
#pragma unroll
                for (int j = 0; j < TN; j++) acc[i][j] += ra[i] * rb[j];
        }
        __syncthreads();
    }

#pragma unroll
    for (int i = 0; i < TM; i++) {
        int mm = m0 + tr + i;
        if (mm >= M) continue;
#pragma unroll
        for (int j = 0; j < TN; j++) {
            int n = n0 + tc + j;
            if (n >= N) continue;
            float v = acc[i][j];
            if (act == 2) { atomicAdd(&C[(size_t)mm * N + n], v); continue; }
            if (bias) v += bias[n];
            if (act == 1) v = v > 0.f ? v : slope * v;
            C[(size_t)mm * N + n] = v;
        }
    }
}

// ---------------- GAT: CSR build ----------------
__global__ void k_cnt2(const int* __restrict__ ei)
{
    int i = blockIdx.x * blockDim.x + threadIdx.x;
    if (i < EE) atomicAdd(&g_cnt[ei[EE + i]], 1);
}
__global__ void k_scan()
{
    __shared__ int part[256];
    int tid = threadIdx.x;
    int base = tid * 9;
    int loc[9]; int s = 0;
#pragma unroll
    for (int i = 0; i < 9; i++) {
        int idx = base + i;
        int c = (idx < NN) ? g_cnt[idx] : 0;
        loc[i] = s; s += c;
    }
    part[tid] = s;
    __syncthreads();
    for (int o = 1; o < 256; o <<= 1) {
        int v = (tid >= o) ? part[tid - o] : 0;
        __syncthreads();
        part[tid] += v;
        __syncthreads();
    }
    int off = (tid > 0) ? part[tid - 1] : 0;
#pragma unroll
    for (int i = 0; i < 9; i++) {
        int idx = base + i;
        if (idx < NN) { g_off[idx] = off + loc[i]; g_cnt[idx] = off + loc[i]; }
    }
    if (tid == 255) g_off[NN] = part[255];
}
__global__ void k_scatter(const int* __restrict__ ei)
{
    int i = blockIdx.x * blockDim.x + threadIdx.x;
    if (i >= ETOT) return;
    int dst = (i < EE) ? ei[EE + i] : i - EE;
    int pos = atomicAdd(&g_cnt[dst], 1);
    g_sorted[pos] = i;
}

// ---------------- GAT: single-pass online softmax + aggregation ----------------
__global__ void __launch_bounds__(256)
k_gat(const int* __restrict__ ei, const float* __restrict__ att,
      const float* __restrict__ gbias)
{
    const int d = blockIdx.x;
    const int wid = threadIdx.x >> 5, lane = threadIdx.x & 31;
    const int beg = g_off[d], nE = g_off[d + 1] - beg;
    const int cb = wid * CC + lane * 4;

    const float4 rv = *reinterpret_cast<const float4*>(&g_xlr[(size_t)d * HC2 + HC + cb]);
    const float4 av = *reinterpret_cast<const float4*>(&att[cb]);

    float m = -1e30f, den = 0.f;
    float a0 = 0.f, a1 = 0.f, a2 = 0.f, a3 = 0.f;

    int e0 = g_sorted[beg];
    int src = (e0 < EE) ? ei[e0] : e0 - EE;
    float4 xv = *reinterpret_cast<const float4*>(&g_xlr[(size_t)src * HC2 + cb]);

    for (int j = 0; j < nE; ++j) {
        float4 cur = xv;
        if (j + 1 < nE) {
            int e1 = g_sorted[beg + j + 1];
            int s1 = (e1 < EE) ? ei[e1] : e1 - EE;
            xv = *reinterpret_cast<const float4*>(&g_xlr[(size_t)s1 * HC2 + cb]);
        }
        float z0 = cur.x + rv.x; z0 = z0 > 0.f ? z0 : 0.2f * z0;
        float z1 = cur.y + rv.y; z1 = z1 > 0.f ? z1 : 0.2f * z1;
        float z2 = cur.z + rv.z; z2 = z2 > 0.f ? z2 : 0.2f * z2;
        float z3 = cur.w + rv.w; z3 = z3 > 0.f ? z3 : 0.2f * z3;
        float s = z0 * av.x + z1 * av.y + z2 * av.z + z3 * av.w;
#pragma unroll
        for (int o = 16; o; o >>= 1) s += __shfl_xor_sync(0xffffffffu, s, o);

        float mn = fmaxf(m, s);
        float sc = __expf(m - mn);
        float ex = __expf(s - mn);
        den = den * sc + ex;
        a0 = a0 * sc + ex * cur.x;
        a1 = a1 * sc + ex * cur.y;
        a2 = a2 * sc + ex * cur.z;
        a3 = a3 * sc + ex * cur.w;
        m = mn;
    }
    float inv = 1.f / den;
    const float4 gb = *reinterpret_cast<const float4*>(&gbias[cb]);
    __half2 o01 = __floats2half2_rn(a0 * inv + gb.x, a1 * inv + gb.y);
    __half2 o23 = __floats2half2_rn(a2 * inv + gb.z, a3 * inv + gb.w);
    __half2* dst = reinterpret_cast<__half2*>(&g_gath[(size_t)d * HC + cb]);
    dst[0] = o01;
    dst[1] = o23;
}

// ---------------- pair features (half reads, __hmul2) ----------------
__global__ void k_feats(const int* __restrict__ pos, const int* __restrict__ neg)
{
    int p = blockIdx.x;
    int mi, di;
    if (p < PP) { mi = pos[p * 2]; di = pos[p * 2 + 1]; }
    else        { mi = neg[(p - PP) * 2]; di = neg[(p - PP) * 2 + 1]; }
    const __half2* a = reinterpret_cast<const __half2*>(g_cnnh + (size_t)mi * FPAD);
    const __half2* b = reinterpret_cast<const __half2*>(g_cnnh + (size_t)(NM + di) * FPAD);
    __half2* f = reinterpret_cast<__half2*>(g_featsh + (size_t)p * FPAD);
    for (int i = threadIdx.x; i < FPAD / 2; i += blockDim.x)
        f[i] = __hmul2(a[i], b[i]);
}

// ---------------- launcher ----------------
static inline int cdiv(int a, int b) { return (a + b - 1) / b; }

extern "C" void kernel_launch(void* const* d_in, const int* in_sizes, int n_in,
                              void* d_out, int out_size)
{
    const float* mic   = (const float*)d_in[0];
    const float* dis   = (const float*)d_in[1];
    const int*   ei    = (const int*)  d_in[2];
    const int*   pos   = (const int*)  d_in[3];
    const int*   neg   = (const int*)  d_in[4];
    const float* W_mic = (const float*)d_in[6];
    const float* W_dis = (const float*)d_in[7];
    const float* Wl    = (const float*)d_in[8];
    const float* bl    = (const float*)d_in[9];
    const float* Wr    = (const float*)d_in[10];
    const float* br    = (const float*)d_in[11];
    const float* att   = (const float*)d_in[12];
    const float* gbias = (const float*)d_in[13];
    const float* cw1   = (const float*)d_in[14];
    const float* cb1   = (const float*)d_in[15];
    const float* cw4   = (const float*)d_in[16];
    const float* cb4   = (const float*)d_in[17];
    const float* cw16  = (const float*)d_in[18];
    const float* cb16  = (const float*)d_in[19];
    const float* cw32  = (const float*)d_in[20];
    const float* cb32  = (const float*)d_in[21];
    const float* mw1   = (const float*)d_in[22];
    const float* mb1   = (const float*)d_in[23];
    const float* mw2   = (const float*)d_in[24];
    const float* mb2   = (const float*)d_in[25];
    const float* mw3   = (const float*)d_in[26];
    const float* mb3   = (const float*)d_in[27];
    const float* mw4   = (const float*)d_in[28];
    float* out = (float*)d_out;

    float *p_h, *p_xlr, *p_blr, *p_cnn, *p_cb;
    __half *p_hh, *p_gath, *p_cnnh, *p_feats, *p_h1, *p_h2;
    __half *p_w1t, *p_w2t, *p_w3t, *p_wlrt, *p_bt;
    cudaGetSymbolAddress((void**)&p_h,     g_h);
    cudaGetSymbolAddress((void**)&p_hh,    g_hh);
    cudaGetSymbolAddress((void**)&p_xlr,   g_xlr);
    cudaGetSymbolAddress((void**)&p_blr,   g_blr);
    cudaGetSymbolAddress((void**)&p_cnn,   g_cnn);
    cudaGetSymbolAddress((void**)&p_cb,    g_cb);
    cudaGetSymbolAddress((void**)&p_gath,  g_gath);
    cudaGetSymbolAddress((void**)&p_cnnh,  g_cnnh);
    cudaGetSymbolAddress((void**)&p_feats, g_featsh);
    cudaGetSymbolAddress((void**)&p_h1,    g_h1h);
    cudaGetSymbolAddress((void**)&p_h2,    g_h2h);
    cudaGetSymbolAddress((void**)&p_w1t,   g_w1th);
    cudaGetSymbolAddress((void**)&p_w2t,   g_w2th);
    cudaGetSymbolAddress((void**)&p_w3t,   g_w3th);
    cudaGetSymbolAddress((void**)&p_wlrt,  g_wlrth);
    cudaGetSymbolAddress((void**)&p_bt,    g_bth);

    const int full = 2 * NPAIR + NN * FDIM;
    float* cnn = (out_size >= full) ? (out + 2 * NPAIR) : p_cnn;
    int write_labels = (out_size >= 2 * NPAIR) ? 1 : 0;

    cudaFuncSetAttribute(gemm_hc, cudaFuncAttributeMaxDynamicSharedMemorySize, SMEM_HC);

    dim3 blk(256);
    dim3 tblk(32, 8);

    // weight preps (independent)
    k_transp<<<dim3(CC / 32, HC / 32), tblk>>>(Wl, p_wlrt,           CC, HC, CC, HC);
    k_transp<<<dim3(CC / 32, HC / 32), tblk>>>(Wr, p_wlrt + HC * CC, CC, HC, CC, HC);
    k_transp<<<dim3(FPAD / 32, D1P / 32), tblk>>>(mw1, p_w1t, FDIM, D1, FPAD, D1P);
    k_transp<<<dim3(D1P / 32, D2NT / 32), tblk>>>(mw2, p_w2t, D1, D2, D1P, D2NT);
    k_transp<<<dim3(D2P / 32, D3NT / 32), tblk>>>(mw3, p_w3t, D2, D3, D2P, D3NT);
    k_bbuild<<<cdiv(FPAD * HC, 256), 256>>>(cw1, cb1, cw4, cb4, cw16, cb16, cw32, cb32);

    // zero/init + CSR build
    k_zero_init<<<cdiv(NNP * CC, 256), 256>>>(p_h, NNP * CC, out, write_labels, bl, br);
    k_cnt2<<<cdiv(EE, 256), 256>>>(ei);
    k_scan<<<1, 256>>>();
    k_scatter<<<cdiv(ETOT, 256), 256>>>(ei);

    // h = concat(mic @ W_mic, dis @ W_dis)  (split-K + atomic add)
    sgemm<<<dim3(1, cdiv(NM, BM), 8), blk>>>(mic, W_mic, nullptr, p_h,           NM, CC, NM, 2, 0.f);
    sgemm<<<dim3(1, cdiv(ND, BM), 4), blk>>>(dis, W_dis, nullptr, p_h + NM * CC, ND, CC, ND, 2, 0.f);
    k_f2h<<<cdiv(NNP * CC, 256), 256>>>(p_h, p_hh, NNP * CC);

    // xl|xr in one fp16 tensor GEMM
    gemm_hc<<<dim3(HC2 / 128, NNP / 128), blk, SMEM_HC>>>(p_hh, p_wlrt, p_blr, p_xlr, HC2, CC, HC2, NNP, 1.0f, 1, nullptr, nullptr, nullptr, 0);

    // single-pass GAT -> half(gat + gbias)
    k_gat<<<NN, 256>>>(ei, att, gbias);

    // CNN as one tensor GEMM; dual write: fp32 -> cnn(out), half -> g_cnnh
    gemm_hc<<<dim3(FPAD / 128, NNP / 128), blk, SMEM_HC>>>(p_gath, p_bt, p_cb, cnn, FDIM, HC, FDIM, NN, 0.0f, 1, nullptr, nullptr, p_cnnh, FPAD);

    // pair features (half) + fp16 tensor-core MLP; layer 3 fuses the final GEMV
    k_feats<<<NPAIR, 256>>>(pos, neg);
    gemm_hc<<<dim3(D1P / 128, NPAIR / 128), blk, SMEM_HC>>>(p_feats, p_w1t, mb1, p_h1, D1, FPAD, D1P, NPAIR, 0.01f, 0, nullptr, nullptr, nullptr, 0);
    gemm_hc<<<dim3(D2NT / 128, NPAIR / 128), blk, SMEM_HC>>>(p_h1, p_w2t, mb2, p_h2, D2, D1P, D2P, NPAIR, 0.01f, 0, nullptr, nullptr, nullptr, 0);
    gemm_hc<<<dim3(D3NT / 128, NPAIR / 128), blk, SMEM_HC>>>(p_h2, p_w3t, mb3, nullptr, D3, D2P, D3P, NPAIR, 0.01f, 0, mw4, out, nullptr, 0);
    k_sig<<<cdiv(NPAIR, 256), 256>>>(out);
}

// round 16
// speedup vs baseline: 1.0192x; 1.0192x over previous
#include <cuda_runtime.h>
#include <cuda_fp16.h>
#include <cstdint>

// ---------------- problem dimensions ----------------
#define NM    1500
#define NMP   1536          // NM padded (M and K) for tensor GEMM
#define ND    800
#define NDP   896           // ND padded to mult of 128 (M)
#define NDK   832           // ND padded to mult of 64 (K)
#define NN    2300
#define NNP   2304
#define CC    128
#define HH    8
#define HC    1024
#define HC2   2048
#define EE    80000
#define ETOT  (EE + NN)
#define PP    40000
#define NPAIR 80000
#define FDIM  2778
#define FPAD  2816
#define D1    1389
#define D1P   1408
#define D2    694
#define D2P   704
#define D2NT  768
#define D3    463
#define D3P   464
#define D3NT  512

// ---------------- scratch ----------------
__device__ __half   g_micH [NMP * NMP];     // padded half mic
__device__ __half   g_disH [NDP * NDK];     // padded half dis
__device__ __half   g_hh   [NNP * CC];
__device__ float    g_xlr  [NNP * HC2];
__device__ float    g_blr  [HC2];
__device__ float    g_zb   [CC];            // zero bias
__device__ __half   g_gath [NNP * HC];
__device__ float    g_cnn  [NN * FDIM];
__device__ int      g_cnt  [NN];
__device__ int      g_off  [NN + 1];
__device__ int      g_sorted[ETOT];
__device__ __half   g_featsh[(size_t)NPAIR * FPAD];
__device__ __half   g_h1h  [(size_t)NPAIR * D1P];
__device__ __half   g_h2h  [(size_t)NPAIR * D2P];
__device__ __half   g_w1th [(size_t)D1P  * FPAD];
__device__ __half   g_w2th [(size_t)D2NT * D1P];
__device__ __half   g_w3th [(size_t)D3NT * D2P];
__device__ __half   g_wlrth[HC2 * CC];
__device__ __half   g_wmt  [CC * NMP];      // W_mic^T fp16 [128][1536]
__device__ __half   g_wdt  [CC * NDK];      // W_dis^T fp16 [128][832]
__device__ __half   g_bth  [(size_t)FPAD * HC];
__device__ float    g_cb   [FPAD];

// ---------------- fp16 mma.sync GEMM, BK=64, 3-stage, occ 2 ----------------
#define HROWB 72
#define HTILE2 (128 * HROWB * 2)
#define HSTG2  (2 * HTILE2)
#define SMEM_HC (3 * HSTG2)

#define LDSM_X4(r0, r1, r2, r3, addr) \
    asm volatile("ldmatrix.sync.aligned.m8n8.x4.shared.b16 {%0,%1,%2,%3}, [%4];" \
        : "=r"(r0), "=r"(r1), "=r"(r2), "=r"(r3) : "r"(addr))

__global__ void __launch_bounds__(256, 2)
gemm_hc(const __half* __restrict__ A, const __half* __restrict__ Bt,
        const float* __restrict__ bias, void* __restrict__ Cv,
        int Nreal, int Kp, int ldc, int Mreal, float slope, int fp32_out,
        const float* __restrict__ dotw, float* __restrict__ dotout)
{
    extern __shared__ __half sm[];
    const int tid  = threadIdx.x;
    const int lane = tid & 31, wid = tid >> 5;
    const int g = lane >> 2, tg = lane & 3;
    const int wm = wid & 1, wn = wid >> 1;
    const int m0 = blockIdx.y * 128, n0 = blockIdx.x * 128;
    const unsigned smb = (unsigned)__cvta_generic_to_shared(sm);

    float acc[4][4][4];
#pragma unroll
    for (int a = 0; a < 4; a++)
#pragma unroll
        for (int b = 0; b < 4; b++)
#pragma unroll
            for (int c = 0; c < 4; c++) acc[a][b][c] = 0.f;

    const unsigned a_off = (unsigned)(((lane & 15) * HROWB + (lane >> 4) * 8) * 2);
    const unsigned b_off = (unsigned)(((((lane >> 4) << 3) + (lane & 7)) * HROWB
                                      + ((lane >> 3) & 1) * 8) * 2);

    auto fill = [&](int s, int kt) {
        unsigned ab = smb + (unsigned)s * HSTG2;
        unsigned bb = ab + HTILE2;
#pragma unroll
        for (int p = 0; p < 4; p++) {
            int i = p * 256 + tid;
            int row = i >> 3, c = i & 7;
            unsigned off = (unsigned)((row * HROWB + c * 8) * 2);
            const __half* srcA = A  + (size_t)(m0 + row) * Kp + kt + c * 8;
            const __half* srcB = Bt + (size_t)(n0 + row) * Kp + kt + c * 8;
            asm volatile("cp.async.cg.shared.global [%0], [%1], 16;" :: "r"(ab + off), "l"(srcA));
            asm volatile("cp.async.cg.shared.global [%0], [%1], 16;" :: "r"(bb + off), "l"(srcB));
        }
        asm volatile("cp.async.commit_group;" ::: "memory");
    };

    const int T = Kp >> 6;
    fill(0, 0);
    if (T > 1) fill(1, 64);

    for (int t = 0; t < T; ++t) {
        if (t < T - 1) asm volatile("cp.async.wait_group 1;" ::: "memory");
        else           asm volatile("cp.async.wait_group 0;" ::: "memory");
        __syncthreads();
        if (t + 2 < T) fill((t + 2) % 3, (t + 2) * 64);

        unsigned ab = smb + (unsigned)(t % 3) * HSTG2;
        unsigned bb = ab + HTILE2;
#pragma unroll
        for (int kk = 0; kk < 4; ++kk) {
            const unsigned kb = (unsigned)(kk * 32);
            unsigned a[4][4], b[2][4];
#pragma unroll
            for (int mt = 0; mt < 4; ++mt) {
                unsigned ad = ab + (unsigned)((wm * 64 + mt * 16) * HROWB * 2) + a_off + kb;
                LDSM_X4(a[mt][0], a[mt][1], a[mt][2], a[mt][3], ad);
            }
#pragma unroll
            for (int np = 0; np < 2; ++np) {
                unsigned bd = bb + (unsigned)((wn * 32 + np * 16) * HROWB * 2) + b_off + kb;
                LDSM_X4(b[np][0], b[np][1], b[np][2], b[np][3], bd);
            }
#pragma unroll
            for (int mt = 0; mt < 4; ++mt)
#pragma unroll
                for (int nt = 0; nt < 4; ++nt) {
                    unsigned b0 = b[nt >> 1][(nt & 1) * 2];
                    unsigned b1 = b[nt >> 1][(nt & 1) * 2 + 1];
                    asm volatile(
                        "mma.sync.aligned.m16n8k16.row.col.f32.f16.f16.f32 "
                        "{%0,%1,%2,%3}, {%4,%5,%6,%7}, {%8,%9}, {%0,%1,%2,%3};\n"
                        : "+f"(acc[mt][nt][0]), "+f"(acc[mt][nt][1]),
                          "+f"(acc[mt][nt][2]), "+f"(acc[mt][nt][3])
                        : "r"(a[mt][0]), "r"(a[mt][1]), "r"(a[mt][2]), "r"(a[mt][3]),
                          "r"(b0), "r"(b1));
                }
        }
    }

    if (dotw) {
        float dsum[4][2];
#pragma unroll
        for (int mt = 0; mt < 4; ++mt) { dsum[mt][0] = 0.f; dsum[mt][1] = 0.f; }
#pragma unroll
        for (int mt = 0; mt < 4; ++mt)
#pragma unroll
            for (int nt = 0; nt < 4; ++nt) {
                int c0 = n0 + wn * 32 + nt * 8 + 2 * tg;
#pragma unroll
                for (int hr = 0; hr < 2; ++hr) {
                    float p = 0.f;
                    if (c0 < Nreal) {
                        float v = acc[mt][nt][hr * 2] + __ldg(&bias[c0]);
                        v = v > 0.f ? v : slope * v;
                        p += v * __ldg(&dotw[c0]);
                    }
                    if (c0 + 1 < Nreal) {
                        float v = acc[mt][nt][hr * 2 + 1] + __ldg(&bias[c0 + 1]);
                        v = v > 0.f ? v : slope * v;
                        p += v * __ldg(&dotw[c0 + 1]);
                    }
                    dsum[mt][hr] += p;
                }
            }
#pragma unroll
        for (int mt = 0; mt < 4; ++mt)
#pragma unroll
            for (int hr = 0; hr < 2; ++hr) {
                float p = dsum[mt][hr];
                p += __shfl_down_sync(0xffffffffu, p, 1, 4);
                p += __shfl_down_sync(0xffffffffu, p, 2, 4);
                if (tg == 0) {
                    int r = m0 + wm * 64 + mt * 16 + g + hr * 8;
                    atomicAdd(&dotout[r], p);
                }
            }
        return;
    }

#pragma unroll
    for (int mt = 0; mt < 4; ++mt) {
#pragma unroll
        for (int nt = 0; nt < 4; ++nt) {
            int r0 = m0 + wm * 64 + mt * 16 + g;
            int c0 = n0 + wn * 32 + nt * 8 + 2 * tg;
            if (c0 >= ldc) continue;
#pragma unroll
            for (int hr = 0; hr < 2; ++hr) {
                int r = r0 + hr * 8;
                if (r >= Mreal) continue;
                float v0 = 0.f, v1 = 0.f;
                if (c0 < Nreal) {
                    v0 = acc[mt][nt][hr * 2] + __ldg(&bias[c0]);
                    v0 = v0 > 0.f ? v0 : slope * v0;
                }
                if (c0 + 1 < Nreal) {
                    v1 = acc[mt][nt][hr * 2 + 1] + __ldg(&bias[c0 + 1]);
                    v1 = v1 > 0.f ? v1 : slope * v1;
                }
                if (fp32_out) {
                    *reinterpret_cast<float2*>(&((float*)Cv)[(size_t)r * ldc + c0])
                        = make_float2(v0, v1);
                } else {
                    *reinterpret_cast<__half2*>(&((__half*)Cv)[(size_t)r * ldc + c0])
                        = __floats2half2_rn(v0, v1);
                }
            }
        }
    }
}

// ---------------- conv-as-GEMM weight build ----------------
__global__ void k_bbuild(const float* __restrict__ cw1,  const float* __restrict__ cb1,
                         const float* __restrict__ cw4,  const float* __restrict__ cb4,
                         const float* __restrict__ cw16, const float* __restrict__ cb16,
                         const float* __restrict__ cw32, const float* __restrict__ cb32)
{
    int i = blockIdx.x * blockDim.x + threadIdx.x;
    if (i >= FPAD * HC) return;
    int c = i >> 10, k = i & 1023;
    float val = 0.f;
    float bv = 0.f;
    if (c < FDIM) {
        int kh = k >> 7, xx = k & 127;
        const float* w; const float* cb; int kw, o, x0;
        if (c < 768)       { int j = c;        kw = 1;  w = cw1;  cb = cb1;  o = j / 128; x0 = j % 128; }
        else if (c < 1518) { int j = c - 768;  kw = 4;  w = cw4;  cb = cb4;  o = j / 125; x0 = j % 125; }
        else if (c < 2196) { int j = c - 1518; kw = 16; w = cw16; cb = cb16; o = j / 113; x0 = j % 113; }
        else               { int j = c - 2196; kw = 32; w = cw32; cb = cb32; o = j / 97;  x0 = j % 97;  }
        int dx = xx - x0;
        if (dx >= 0 && dx < kw) val = w[(o * 8 + kh) * kw + dx];
        bv = cb[o];
    }
    g_bth[(size_t)c * HC + k] = __float2half_rn(val);
    if (k == 0) g_cb[c] = bv;
}

// ---------------- tiled transpose + fp16: dst[n][k] = src[k][n] ----------------
__global__ void k_transp(const float* __restrict__ src, __half* __restrict__ dst,
                         int Ktrue, int Ntrue, int Kp, int Npad)
{
    __shared__ float t[32][33];
    int k0 = blockIdx.x * 32, n0 = blockIdx.y * 32;
    int tx = threadIdx.x, ty = threadIdx.y;
#pragma unroll
    for (int i = 0; i < 4; i++) {
        int k = k0 + ty + i * 8, n = n0 + tx;
        t[ty + i * 8][tx] = (k < Ktrue && n < Ntrue) ? src[(size_t)k * Ntrue + n] : 0.f;
    }
    __syncthreads();
#pragma unroll
    for (int i = 0; i < 4; i++) {
        int n = n0 + ty + i * 8, k = k0 + tx;
        if (n < Npad && k < Kp)
            dst[(size_t)n * Kp + k] = __float2half_rn(t[tx][ty + i * 8]);
    }
}

// fp32 -> padded fp16 input copy (zero fill)
__global__ void k_inpad(const float* __restrict__ src, __half* __restrict__ dst,
                        int R, int K, int Rp, int Kp)
{
    int i = blockIdx.x * blockDim.x + threadIdx.x;
    if (i >= Rp * Kp) return;
    int r = i / Kp, k = i - r * Kp;
    float v = (r < R && k < K) ? src[(size_t)r * K + k] : 0.f;
    dst[i] = __float2half_rn(v);
}

// init: CSR counts, pred zero, labels, bias concat, zero-bias, gath + hh pad rows
__global__ void k_zero_init(float* out, int write_labels,
                            const float* __restrict__ bl, const float* __restrict__ br)
{
    int i = blockIdx.x * blockDim.x + threadIdx.x;
    if (i < NN) g_cnt[i] = 1;
    if (i < HC) { g_blr[i] = bl[i]; g_blr[HC + i] = br[i]; }
    if (i < CC) g_zb[i] = 0.f;
    if (i < (NNP - NN) * HC) g_gath[NN * HC + i] = __float2half_rn(0.f);
    if (i < (NNP - NN) * CC) g_hh[NN * CC + i] = __float2half_rn(0.f);
    if (i < NPAIR) {
        out[i] = 0.f;
        if (write_labels) out[NPAIR + i] = (i < PP) ? 1.f : 0.f;
    }
}

__global__ void k_sig(float* __restrict__ out)
{
    int i = blockIdx.x * blockDim.x + threadIdx.x;
    if (i < NPAIR) out[i] = 1.f / (1.f + expf(-out[i]));
}

// ---------------- GAT: CSR build ----------------
__global__ void k_cnt2(const int* __restrict__ ei)
{
    int i = blockIdx.x * blockDim.x + threadIdx.x;
    if (i < EE) atomicAdd(&g_cnt[ei[EE + i]], 1);
}
__global__ void k_scan()
{
    __shared__ int part[256];
    int tid = threadIdx.x;
    int base = tid * 9;
    int loc[9]; int s = 0;
#pragma unroll
    for (int i = 0; i < 9; i++) {
        int idx = base + i;
        int c = (idx < NN) ? g_cnt[idx] : 0;
        loc[i] = s; s += c;
    }
    part[tid] = s;
    __syncthreads();
    for (int o = 1; o < 256; o <<= 1) {
        int v = (tid >= o) ? part[tid - o] : 0;
        __syncthreads();
        part[tid] += v;
        __syncthreads();
    }
    int off = (tid > 0) ? part[tid - 1] : 0;
#pragma unroll
    for (int i = 0; i < 9; i++) {
        int idx = base + i;
        if (idx < NN) { g_off[idx] = off + loc[i]; g_cnt[idx] = off + loc[i]; }
    }
    if (tid == 255) g_off[NN] = part[255];
}
__global__ void k_scatter(const int* __restrict__ ei)
{
    int i = blockIdx.x * blockDim.x + threadIdx.x;
    if (i >= ETOT) return;
    int dst = (i < EE) ? ei[EE + i] : i - EE;
    int pos = atomicAdd(&g_cnt[dst], 1);
    g_sorted[pos] = i;
}

// ---------------- GAT: single-pass online softmax + aggregation ----------------
__global__ void __launch_bounds__(256)
k_gat(const int* __restrict__ ei, const float* __restrict__ att,
      const float* __restrict__ gbias)
{
    const int d = blockIdx.x;
    const int wid = threadIdx.x >> 5, lane = threadIdx.x & 31;
    const int beg = g_off[d], nE = g_off[d + 1] - beg;
    const int cb = wid * CC + lane * 4;

    const float4 rv = *reinterpret_cast<const float4*>(&g_xlr[(size_t)d * HC2 + HC + cb]);
    const float4 av = *reinterpret_cast<const float4*>(&att[cb]);

    float m = -1e30f, den = 0.f;
    float a0 = 0.f, a1 = 0.f, a2 = 0.f, a3 = 0.f;

    int e0 = g_sorted[beg];
    int src = (e0 < EE) ? ei[e0] : e0 - EE;
    float4 xv = *reinterpret_cast<const float4*>(&g_xlr[(size_t)src * HC2 + cb]);

    for (int j = 0; j < nE; ++j) {
        float4 cur = xv;
        if (j + 1 < nE) {
            int e1 = g_sorted[beg + j + 1];
            int s1 = (e1 < EE) ? ei[e1] : e1 - EE;
            xv = *reinterpret_cast<const float4*>(&g_xlr[(size_t)s1 * HC2 + cb]);
        }
        float z0 = cur.x + rv.x; z0 = z0 > 0.f ? z0 : 0.2f * z0;
        float z1 = cur.y + rv.y; z1 = z1 > 0.f ? z1 : 0.2f * z1;
        float z2 = cur.z + rv.z; z2 = z2 > 0.f ? z2 : 0.2f * z2;
        float z3 = cur.w + rv.w; z3 = z3 > 0.f ? z3 : 0.2f * z3;
        float s = z0 * av.x + z1 * av.y + z2 * av.z + z3 * av.w;
#pragma unroll
        for (int o = 16; o; o >>= 1) s += __shfl_xor_sync(0xffffffffu, s, o);

        float mn = fmaxf(m, s);
        float sc = __expf(m - mn);
        float ex = __expf(s - mn);
        den = den * sc + ex;
        a0 = a0 * sc + ex * cur.x;
        a1 = a1 * sc + ex * cur.y;
        a2 = a2 * sc + ex * cur.z;
        a3 = a3 * sc + ex * cur.w;
        m = mn;
    }
    float inv = 1.f / den;
    const float4 gb = *reinterpret_cast<const float4*>(&gbias[cb]);
    __half2 o01 = __floats2half2_rn(a0 * inv + gb.x, a1 * inv + gb.y);
    __half2 o23 = __floats2half2_rn(a2 * inv + gb.z, a3 * inv + gb.w);
    __half2* dst = reinterpret_cast<__half2*>(&g_gath[(size_t)d * HC + cb]);
    dst[0] = o01;
    dst[1] = o23;
}

// ---------------- pair features (fp32 cnn reads) ----------------
__global__ void k_feats(const int* __restrict__ pos, const int* __restrict__ neg,
                        const float* __restrict__ cnn)
{
    int p = blockIdx.x;
    int mi, di;
    if (p < PP) { mi = pos[p * 2]; di = pos[p * 2 + 1]; }
    else        { mi = neg[(p - PP) * 2]; di = neg[(p - PP) * 2 + 1]; }
    const float2* a = reinterpret_cast<const float2*>(cnn + (size_t)mi * FDIM);
    const float2* b = reinterpret_cast<const float2*>(cnn + (size_t)(NM + di) * FDIM);
    __half2* f = reinterpret_cast<__half2*>(g_featsh + (size_t)p * FPAD);
    for (int i = threadIdx.x; i < FPAD / 2; i += blockDim.x) {
        float v0 = 0.f, v1 = 0.f;
        if (i < FDIM / 2) {
            float2 av = a[i], bv = b[i];
            v0 = av.x * bv.x; v1 = av.y * bv.y;
        }
        f[i] = __floats2half2_rn(v0, v1);
    }
}

// ---------------- launcher ----------------
static inline int cdiv(int a, int b) { return (a + b - 1) / b; }

extern "C" void kernel_launch(void* const* d_in, const int* in_sizes, int n_in,
                              void* d_out, int out_size)
{
    const float* mic   = (const float*)d_in[0];
    const float* dis   = (const float*)d_in[1];
    const int*   ei    = (const int*)  d_in[2];
    const int*   pos   = (const int*)  d_in[3];
    const int*   neg   = (const int*)  d_in[4];
    const float* W_mic = (const float*)d_in[6];
    const float* W_dis = (const float*)d_in[7];
    const float* Wl    = (const float*)d_in[8];
    const float* bl    = (const float*)d_in[9];
    const float* Wr    = (const float*)d_in[10];
    const float* br    = (const float*)d_in[11];
    const float* att   = (const float*)d_in[12];
    const float* gbias = (const float*)d_in[13];
    const float* cw1   = (const float*)d_in[14];
    const float* cb1   = (const float*)d_in[15];
    const float* cw4   = (const float*)d_in[16];
    const float* cb4   = (const float*)d_in[17];
    const float* cw16  = (const float*)d_in[18];
    const float* cb16  = (const float*)d_in[19];
    const float* cw32  = (const float*)d_in[20];
    const float* cb32  = (const float*)d_in[21];
    const float* mw1   = (const float*)d_in[22];
    const float* mb1   = (const float*)d_in[23];
    const float* mw2   = (const float*)d_in[24];
    const float* mb2   = (const float*)d_in[25];
    const float* mw3   = (const float*)d_in[26];
    const float* mb3   = (const float*)d_in[27];
    const float* mw4   = (const float*)d_in[28];
    float* out = (float*)d_out;

    float *p_xlr, *p_blr, *p_cnn, *p_cb, *p_zb;
    __half *p_micH, *p_disH, *p_hh, *p_gath, *p_feats, *p_h1, *p_h2;
    __half *p_w1t, *p_w2t, *p_w3t, *p_wlrt, *p_wmt, *p_wdt, *p_bt;
    cudaGetSymbolAddress((void**)&p_micH,  g_micH);
    cudaGetSymbolAddress((void**)&p_disH,  g_disH);
    cudaGetSymbolAddress((void**)&p_hh,    g_hh);
    cudaGetSymbolAddress((void**)&p_xlr,   g_xlr);
    cudaGetSymbolAddress((void**)&p_blr,   g_blr);
    cudaGetSymbolAddress((void**)&p_zb,    g_zb);
    cudaGetSymbolAddress((void**)&p_cnn,   g_cnn);
    cudaGetSymbolAddress((void**)&p_cb,    g_cb);
    cudaGetSymbolAddress((void**)&p_gath,  g_gath);
    cudaGetSymbolAddress((void**)&p_feats, g_featsh);
    cudaGetSymbolAddress((void**)&p_h1,    g_h1h);
    cudaGetSymbolAddress((void**)&p_h2,    g_h2h);
    cudaGetSymbolAddress((void**)&p_w1t,   g_w1th);
    cudaGetSymbolAddress((void**)&p_w2t,   g_w2th);
    cudaGetSymbolAddress((void**)&p_w3t,   g_w3th);
    cudaGetSymbolAddress((void**)&p_wlrt,  g_wlrth);
    cudaGetSymbolAddress((void**)&p_wmt,   g_wmt);
    cudaGetSymbolAddress((void**)&p_wdt,   g_wdt);
    cudaGetSymbolAddress((void**)&p_bt,    g_bth);

    const int full = 2 * NPAIR + NN * FDIM;
    float* cnn = (out_size >= full) ? (out + 2 * NPAIR) : p_cnn;
    int write_labels = (out_size >= 2 * NPAIR) ? 1 : 0;

    cudaFuncSetAttribute(gemm_hc, cudaFuncAttributeMaxDynamicSharedMemorySize, SMEM_HC);

    dim3 blk(256);
    dim3 tblk(32, 8);

    // weight preps (independent)
    k_transp<<<dim3(CC / 32, HC / 32), tblk>>>(Wl, p_wlrt,           CC, HC, CC, HC);
    k_transp<<<dim3(CC / 32, HC / 32), tblk>>>(Wr, p_wlrt + HC * CC, CC, HC, CC, HC);
    k_transp<<<dim3(NMP / 32, CC / 32), tblk>>>(W_mic, p_wmt, NM, CC, NMP, CC);
    k_transp<<<dim3(NDK / 32, CC / 32), tblk>>>(W_dis, p_wdt, ND, CC, NDK, CC);
    k_transp<<<dim3(FPAD / 32, D1P / 32), tblk>>>(mw1, p_w1t, FDIM, D1, FPAD, D1P);
    k_transp<<<dim3(D1P / 32, D2NT / 32), tblk>>>(mw2, p_w2t, D1, D2, D1P, D2NT);
    k_transp<<<dim3(D2P / 32, D3NT / 32), tblk>>>(mw3, p_w3t, D2, D3, D2P, D3NT);
    k_bbuild<<<cdiv(FPAD * HC, 256), 256>>>(cw1, cb1, cw4, cb4, cw16, cb16, cw32, cb32);

    // padded half input copies
    k_inpad<<<cdiv(NMP * NMP, 256), 256>>>(mic, p_micH, NM, NM, NMP, NMP);
    k_inpad<<<cdiv(NDP * NDK, 256), 256>>>(dis, p_disH, ND, ND, NDP, NDK);

    // init + CSR build
    k_zero_init<<<cdiv(NPAIR, 256), 256>>>(out, write_labels, bl, br);
    k_cnt2<<<cdiv(EE, 256), 256>>>(ei);
    k_scan<<<1, 256>>>();
    k_scatter<<<cdiv(ETOT, 256), 256>>>(ei);

    // h (fp16) = concat(mic @ W_mic, dis @ W_dis) via tensor GEMMs
    gemm_hc<<<dim3(1, NMP / 128), blk, SMEM_HC>>>(p_micH, p_wmt, p_zb, p_hh,            CC, NMP, CC, NM, 1.0f, 0, nullptr, nullptr);
    gemm_hc<<<dim3(1, NDP / 128), blk, SMEM_HC>>>(p_disH, p_wdt, p_zb, p_hh + NM * CC,  CC, NDK, CC, ND, 1.0f, 0, nullptr, nullptr);

    // xl|xr in one fp16 tensor GEMM
    gemm_hc<<<dim3(HC2 / 128, NNP / 128), blk, SMEM_HC>>>(p_hh, p_wlrt, p_blr, p_xlr, HC2, CC, HC2, NNP, 1.0f, 1, nullptr, nullptr);

    // single-pass GAT -> half(gat + gbias)
    k_gat<<<NN, 256>>>(ei, att, gbias);

    // CNN as one tensor GEMM: cnn = relu(gath @ Bt^T + cb), fp32 out, M-guarded
    gemm_hc<<<dim3(FPAD / 128, NNP / 128), blk, SMEM_HC>>>(p_gath, p_bt, p_cb, cnn, FDIM, HC, FDIM, NN, 0.0f, 1, nullptr, nullptr);

    // pair features + fp16 tensor-core MLP; layer 3 fuses the final GEMV
    k_feats<<<NPAIR, 256>>>(pos, neg, cnn);
    gemm_hc<<<dim3(D1P / 128, NPAIR / 128), blk, SMEM_HC>>>(p_feats, p_w1t, mb1, p_h1, D1, FPAD, D1P, NPAIR, 0.01f, 0, nullptr, nullptr);
    gemm_hc<<<dim3(D2NT / 128, NPAIR / 128), blk, SMEM_HC>>>(p_h1, p_w2t, mb2, p_h2, D2, D1P, D2P, NPAIR, 0.01f, 0, nullptr, nullptr);
    gemm_hc<<<dim3(D3NT / 128, NPAIR / 128), blk, SMEM_HC>>>(p_h2, p_w3t, mb3, nullptr, D3, D2P, D3P, NPAIR, 0.01f, 0, mw4, out);
    k_sig<<<cdiv(NPAIR, 256), 256>>>(out);
}